// round 17
// baseline (speedup 1.0000x reference)
#include <cuda_runtime.h>
#include <cstdint>

#define N_BATCH 256
#define C_DIM   2048
#define HW      49
#define CH      128                    // c-rows per staged chunk
#define ELEMS   (CH * HW)              // 6272 floats per chunk
#define CHUNK_BYTES (ELEMS * 4)        // 25088 B
#define NBUF    3
#define THREADS 288                    // 8 consumer warps + 1 producer warp
#define NCONS   8
#define UNITS_PER_N   8                // 256 channels per unit (2 chunks)
#define TOTAL_UNITS   (N_BATCH * UNITS_PER_N)   // 2048
#define NWORKERS      296              // 2 per SM on 148 SMs
// smem header: full[3], empty[3] mbarriers + ud[4] unit-id ring -> 48 floats
#define SMEM_HDR_FLOATS 48
#define SMEM_FLOATS (SMEM_HDR_FLOATS + 4 * C_DIM + NBUF * ELEMS)
#define SMEM_BYTES  (SMEM_FLOATS * 4)  // 192 + 32768 + 75264 = 108224 B -> 2 CTAs/SM

// Cross-worker scratch (reset counter each launch via rcp_reset kernel)
__device__ float        g_part[UNITS_PER_N][N_BATCH][5][HW];   // ~2 MB
__device__ unsigned int g_count[N_BATCH];
__device__ unsigned int g_unit_ctr;

__device__ __forceinline__ uint32_t smem_u32(const void* p) {
    return (uint32_t)__cvta_generic_to_shared(p);
}
__device__ __forceinline__ void mbar_init(uint32_t mbar, uint32_t count) {
    asm volatile("mbarrier.init.shared::cta.b64 [%0], %1;" :: "r"(mbar), "r"(count) : "memory");
}
__device__ __forceinline__ void mbar_expect_tx(uint32_t mbar, uint32_t bytes) {
    asm volatile("mbarrier.arrive.expect_tx.shared::cta.b64 _, [%0], %1;"
                 :: "r"(mbar), "r"(bytes) : "memory");
}
__device__ __forceinline__ void mbar_arrive(uint32_t mbar) {
    asm volatile("mbarrier.arrive.release.cta.shared::cta.b64 _, [%0];"
                 :: "r"(mbar) : "memory");
}
__device__ __forceinline__ void bulk_g2s(uint32_t smem_dst, const void* gsrc,
                                         uint32_t bytes, uint32_t mbar) {
    asm volatile("cp.async.bulk.shared::cta.global.mbarrier::complete_tx::bytes "
                 "[%0], [%1], %2, [%3];"
                 :: "r"(smem_dst), "l"(gsrc), "r"(bytes), "r"(mbar) : "memory");
}
__device__ __forceinline__ void mbar_wait(uint32_t mbar, uint32_t parity) {
    uint32_t done;
    asm volatile(
        "{\n\t.reg .pred p;\n\t"
        "mbarrier.try_wait.parity.acquire.cta.shared::cta.b64 p, [%1], %2;\n\t"
        "selp.b32 %0, 1, 0, p;\n\t}"
        : "=r"(done) : "r"(mbar), "r"(parity) : "memory");
    if (!done) {
        asm volatile(
            "{\n\t.reg .pred P1;\n\t"
            "WAIT_LOOP_%=:\n\t"
            "mbarrier.try_wait.parity.acquire.cta.shared::cta.b64 P1, [%0], %1, 0x989680;\n\t"
            "@P1 bra.uni WAIT_DONE_%=;\n\t"
            "bra.uni WAIT_LOOP_%=;\n\t"
            "WAIT_DONE_%=:\n\t}"
            :: "r"(mbar), "r"(parity) : "memory");
    }
}
__device__ __forceinline__ void pack_dup(uint64_t& dst, float v) {
    asm("mov.b64 %0, {%1, %1};" : "=l"(dst) : "r"(__float_as_uint(v)));
}
__device__ __forceinline__ void fma2(uint64_t& acc, uint64_t xx, uint64_t ww) {
    asm("fma.rn.f32x2 %0, %1, %2, %0;" : "+l"(acc) : "l"(xx), "l"(ww));
}
__device__ __forceinline__ float ldcg(const float* p) {
    float v; asm("ld.global.cg.f32 %0, [%1];" : "=f"(v) : "l"(p)); return v;
}

__global__ void rcp_reset_kernel() {
    if (threadIdx.x == 0) g_unit_ctr = 0;
    if (threadIdx.x < N_BATCH) g_count[threadIdx.x] = 0;
}

// Persistent workers: each CTA = R9 pipeline (TMA producer warp + 8 consumer
// warps) stealing (n, eighth) units; 8th finisher per n combines + epilogue.
__global__ void __launch_bounds__(THREADS, 2)
rcp_persist_kernel(const float* __restrict__ x, const float* __restrict__ mask,
                   const float* __restrict__ W, const float* __restrict__ bvec,
                   float* __restrict__ out) {
    const int tid  = threadIdx.x;
    const int wid  = tid >> 5;
    const int lane = tid & 31;

    extern __shared__ float smem[];
    uint64_t* mbar_s = reinterpret_cast<uint64_t*>(smem);            // full[3], empty[3]
    int*      ud     = reinterpret_cast<int*>(smem) + 12;            // unit-id ring [4]
    float4*   wpack  = reinterpret_cast<float4*>(smem + SMEM_HDR_FLOATS);
    float*    xs     = smem + SMEM_HDR_FLOATS + 4 * C_DIM;

    const uint32_t full0  = smem_u32(&mbar_s[0]);
    const uint32_t empty0 = smem_u32(&mbar_s[NBUF]);

    if (tid == 0) {
        #pragma unroll
        for (int b = 0; b < NBUF; b++) {
            mbar_init(full0  + 8 * b, 1);
            mbar_init(empty0 + 8 * b, NCONS);
        }
    }
    // Stage W packed {A0w,A1w,D0w,D1w}: W(2,4096), halves at +0/+2048 per row.
    for (int c = tid; c < C_DIM; c += THREADS) {
        wpack[c] = make_float4(W[c], W[4096 + c], W[2048 + c], W[6144 + c]);
    }
    __syncthreads();

    if (wid == NCONS) {
        // ---- Producer: steal units, stream 2 chunks each; stop with -1 ----
        if (lane == 0) {
            int buf = 0, pphase = 1, c = 0;   // pphase=1: flips to 0 before 1st empty-wait
            for (;;) {
                unsigned u = atomicAdd(&g_unit_ctr, 1u);
                ud[(c >> 1) & 3] = (u < TOTAL_UNITS) ? (int)u : -1;  // STS before arrive
                if (u >= TOTAL_UNITS) {
                    mbar_arrive(full0 + 8 * buf);    // wake consumers -> they read -1
                    break;
                }
                const int n = (int)(u >> 3), e = (int)(u & 7);
                const float* base = x + (size_t)n * (C_DIM * HW) + (size_t)(2 * e) * ELEMS;
                #pragma unroll
                for (int k = 0; k < 2; k++) {
                    if (c >= NBUF) mbar_wait(empty0 + 8 * buf, pphase);
                    uint32_t fb = full0 + 8 * buf;
                    mbar_expect_tx(fb, CHUNK_BYTES);
                    bulk_g2s(smem_u32(xs + buf * ELEMS), base + k * ELEMS, CHUNK_BYTES, fb);
                    c++;
                    if (++buf == NBUF) { buf = 0; pphase ^= 1; }
                }
            }
        }
        return;   // producer warp exits after stop (other lanes idle-exit)
    }

    // ---- Consumer warps ----
    int buf = 0, fphase = 0, c = 0;
    const float inv_pi = 0.318309886183790672f;
    for (;;) {
        mbar_wait(full0 + 8 * buf, fphase);
        const int u = ud[(c >> 1) & 3];
        if (u < 0) break;
        const int n = u >> 3, e = u & 7;

        float    s[7]    = {0,0,0,0,0,0,0};
        uint64_t accA[7] = {0,0,0,0,0,0,0};
        uint64_t accD[7] = {0,0,0,0,0,0,0};

        #pragma unroll
        for (int k = 0; k < 2; k++) {
            if (k) mbar_wait(full0 + 8 * buf, fphase);
            const float*      xb  = xs + buf * ELEMS;
            const ulonglong2* wp2 = reinterpret_cast<const ulonglong2*>(wpack + (2 * e + k) * CH);
            #pragma unroll
            for (int it = 0; it < 4; it++) {
                const int cl = lane + 32 * it;
                ulonglong2 w2 = wp2[cl];
                const float* row = xb + cl * HW;
                float xv[6];
                #pragma unroll
                for (int i = 0; i < 6; i++) xv[i] = row[wid + 8 * i];
                #pragma unroll
                for (int i = 0; i < 6; i++) {
                    uint64_t xx; pack_dup(xx, xv[i]);
                    s[i] += xv[i];
                    fma2(accA[i], xx, w2.x);
                    fma2(accD[i], xx, w2.y);
                }
                if (wid == 0) {
                    float x6 = row[48];
                    uint64_t xx; pack_dup(xx, x6);
                    s[6] += x6;
                    fma2(accA[6], xx, w2.x);
                    fma2(accD[6], xx, w2.y);
                }
            }
            __syncwarp();
            if (lane == 0) mbar_arrive(empty0 + 8 * buf);
            c++;
            if (++buf == NBUF) { buf = 0; fphase ^= 1; }
        }

        // Per-unit flush: shuffle-reduce, lane0 writes slot g_part[e][n]
        float* gp = &g_part[e][n][0][0];
        #pragma unroll
        for (int i = 0; i < 7; i++) {
            int p = wid + 8 * i;
            float vs = s[i];
            float u0 = __uint_as_float((uint32_t)(accA[i] & 0xFFFFFFFFu));
            float u1 = __uint_as_float((uint32_t)(accA[i] >> 32));
            float v0 = __uint_as_float((uint32_t)(accD[i] & 0xFFFFFFFFu));
            float v1 = __uint_as_float((uint32_t)(accD[i] >> 32));
            #pragma unroll
            for (int off = 16; off; off >>= 1) {
                vs += __shfl_xor_sync(0xFFFFFFFFu, vs, off);
                u0 += __shfl_xor_sync(0xFFFFFFFFu, u0, off);
                u1 += __shfl_xor_sync(0xFFFFFFFFu, u1, off);
                v0 += __shfl_xor_sync(0xFFFFFFFFu, v0, off);
                v1 += __shfl_xor_sync(0xFFFFFFFFu, v1, off);
            }
            if (lane == 0 && p < HW) {
                gp[0 * HW + p] = vs;
                gp[1 * HW + p] = u0;
                gp[2 * HW + p] = u1;
                gp[3 * HW + p] = v0;
                gp[4 * HW + p] = v1;
            }
        }
        asm volatile("bar.sync 1, %0;" :: "n"(NCONS * 32) : "memory");  // consumers only

        int win = 0;
        if (tid == 0) {
            __threadfence();
            unsigned old = atomicAdd(&g_count[n], 1u);
            win = (old == UNITS_PER_N - 1);
        }
        if (wid == 0) {
            win = __shfl_sync(0xFFFFFFFFu, win, 0);
            if (win) {
                // ---- Epilogue for n: fixed-order 8-slot combine (ldcg) ----
                __threadfence();
                float S[2], A0[2], A1[2], D0[2], D1[2];
                #pragma unroll
                for (int t = 0; t < 2; t++) {
                    int p = lane + 32 * t;
                    S[t] = A0[t] = A1[t] = D0[t] = D1[t] = 0.0f;
                    if (p < HW) {
                        #pragma unroll
                        for (int ee = 0; ee < UNITS_PER_N; ee++) {
                            const float* sp = &g_part[ee][n][0][0];
                            S [t] += ldcg(sp + 0 * HW + p);
                            A0[t] += ldcg(sp + 1 * HW + p);
                            A1[t] += ldcg(sp + 2 * HW + p);
                            D0[t] += ldcg(sp + 3 * HW + p);
                            D1[t] += ldcg(sp + 4 * HW + p);
                        }
                    }
                }
                const float* m = mask + n * HW;
                float m0 = m[lane];
                float m1 = (lane + 32 < HW) ? m[lane + 32] : 0.0f;
                float msum = m0 + m1;
                #pragma unroll
                for (int off = 16; off; off >>= 1)
                    msum += __shfl_xor_sync(0xFFFFFFFFu, msum, off);
                const float thr = msum * (1.0f / 49.0f);

                float bv = (m0 > thr) ? S[0] * (1.0f / (float)C_DIM) : 0.0f;
                int   bi = lane;
                if (lane + 32 < HW) {
                    float v1 = (m1 > thr) ? S[1] * (1.0f / (float)C_DIM) : 0.0f;
                    if (v1 > bv) { bv = v1; bi = lane + 32; }
                }
                #pragma unroll
                for (int off = 16; off; off >>= 1) {
                    float ov = __shfl_xor_sync(0xFFFFFFFFu, bv, off);
                    int   oi = __shfl_xor_sync(0xFFFFFFFFu, bi, off);
                    if (ov > bv || (ov == bv && oi < bi)) { bv = ov; bi = oi; }
                }
                const int pstar = bi;
                const float A0s = (pstar < 32) ? __shfl_sync(0xFFFFFFFFu, A0[0], pstar)
                                               : __shfl_sync(0xFFFFFFFFu, A0[1], pstar - 32);
                const float A1s = (pstar < 32) ? __shfl_sync(0xFFFFFFFFu, A1[0], pstar)
                                               : __shfl_sync(0xFFFFFFFFu, A1[1], pstar - 32);
                const float b0 = bvec[0], b1 = bvec[1];
                const float ai = (float)(pstar / 7);
                const float aj = (float)(pstar % 7);

                float dist[2], gap[2];
                float gsum = 0.0f;
                #pragma unroll
                for (int t = 0; t < 2; t++) {
                    int p = lane + 32 * t;
                    if (p < HW) {
                        float pd = fmaxf(A0s + D0[t] + b0, 0.0f);
                        float pa = fmaxf(A1s + D1[t] + b1, 0.0f);
                        if (p == pstar) { pd = 0.0f; pa = 0.0f; }
                        float ri = ((float)(p / 7) - ai) * (1.0f / 7.0f);
                        float rj = ((float)(p % 7) - aj) * (1.0f / 7.0f);
                        float rd = sqrtf(ri * ri + rj * rj);
                        float ra = (atan2f(rj, ri) * inv_pi + 1.0f) * 0.5f;
                        float g  = pa - ra;
                        if (g < 0.0f) g += 1.0f;
                        float dl = pd - rd;
                        dist[t] = dl * dl;
                        gap[t]  = g;
                        gsum   += g;
                    } else { dist[t] = 0.0f; gap[t] = 0.0f; }
                }
                #pragma unroll
                for (int off = 16; off; off >>= 1)
                    gsum += __shfl_xor_sync(0xFFFFFFFFu, gsum, off);
                const float gmean = gsum * (1.0f / 49.0f);
                #pragma unroll
                for (int t = 0; t < 2; t++) {
                    int p = lane + 32 * t;
                    if (p < HW) {
                        float gg = gap[t] - gmean;
                        out[n * HW + p] = dist[t] + gg * gg;
                    }
                }
            }
        }
    }
}

extern "C" void kernel_launch(void* const* d_in, const int* in_sizes, int n_in,
                              void* d_out, int out_size) {
    const float* x    = (const float*)d_in[0];   // (256, 2048, 7, 7)
    const float* mask = (const float*)d_in[1];   // (256, 7, 7)
    const float* W    = (const float*)d_in[2];   // (2, 4096)
    const float* b    = (const float*)d_in[3];   // (2,)
    float* out = (float*)d_out;                  // (256, 7, 7)

    cudaFuncSetAttribute(rcp_persist_kernel,
                         cudaFuncAttributeMaxDynamicSharedMemorySize, SMEM_BYTES);

    rcp_reset_kernel<<<1, 256>>>();
    rcp_persist_kernel<<<NWORKERS, THREADS, SMEM_BYTES>>>(x, mask, W, b, out);
}